// round 10
// baseline (speedup 1.0000x reference)
#include <cuda_runtime.h>
#include <math_constants.h>
#include <cstdint>

// ---------------------------------------------------------------------------
// Problem constants
// ---------------------------------------------------------------------------
namespace {
constexpr int B_  = 64;
constexpr int T_  = 256;
constexpr int DM  = 512;   // d_model
constexpr int H_  = 8;     // heads
constexpr int DK  = 64;    // head dim
constexpr int NTOK = B_ * T_;  // 16384

constexpr int BM = 128, BN = 128, BK = 32;
constexpr int KITERS = DM / BK;   // 16
constexpr int ASTR = 36;          // A smem row stride (floats)  [m][k]
constexpr int BSTR = 136;         // B smem k-row stride (floats) [k][n]
constexpr int ABUFS = BM * ASTR;  // 4608 floats per stage
constexpr int BBUFS = BK * BSTR;  // 4352 floats per stage
constexpr int GEMM_SMEM = 3 * (ABUFS + BBUFS) * 4;   // 107520 B
constexpr int WQKV = H_ * DM * DK;   // 262144
constexpr int WO_OFF = 3 * WQKV;
}

// Scratch (device globals — no allocation allowed in kernel_launch)
__device__ float g_Q[B_ * H_ * T_ * DK];
__device__ float g_K[B_ * H_ * T_ * DK];
__device__ float g_V[B_ * H_ * T_ * DK];
__device__ float g_att[NTOK * DM];
__device__ float g_xT[NTOK * DM];              // tf32-rounded x
__device__ float g_Wt[3 * WQKV + DM * DM];     // tf32-rounded Wq|Wk|Wv|Wo

// ---------------------------------------------------------------------------
// Helpers
// ---------------------------------------------------------------------------
__device__ __forceinline__ uint32_t f2tf32(float f) {
    uint32_t r;
    asm("cvt.rna.tf32.f32 %0, %1;" : "=r"(r) : "f"(f));
    return r;
}
__device__ __forceinline__ float rnd_tf32(float f) {
    return __uint_as_float(f2tf32(f));
}

__device__ __forceinline__ uint32_t smem_u32(const void* p) {
    uint32_t a;
    asm("{ .reg .u64 t; cvta.to.shared.u64 t, %1; cvt.u32.u64 %0, t; }"
        : "=r"(a) : "l"(p));
    return a;
}

__device__ __forceinline__ void cp16(uint32_t dst, const float* src) {
    asm volatile("cp.async.cg.shared.global [%0], [%1], 16;"
                 :: "r"(dst), "l"(src) : "memory");
}
__device__ __forceinline__ void cp_commit() {
    asm volatile("cp.async.commit_group;" ::: "memory");
}
__device__ __forceinline__ void cp_wait0() {
    asm volatile("cp.async.wait_group 0;" ::: "memory");
}
__device__ __forceinline__ void cp_wait1() {
    asm volatile("cp.async.wait_group 1;" ::: "memory");
}

__device__ __forceinline__ void mma_tf32(float& d0, float& d1, float& d2, float& d3,
                                         uint32_t a0, uint32_t a1, uint32_t a2, uint32_t a3,
                                         uint32_t b0, uint32_t b1) {
    asm volatile(
        "mma.sync.aligned.m16n8k8.row.col.f32.tf32.tf32.f32 "
        "{%0,%1,%2,%3}, {%4,%5,%6,%7}, {%8,%9}, {%0,%1,%2,%3};"
        : "+f"(d0), "+f"(d1), "+f"(d2), "+f"(d3)
        : "r"(a0), "r"(a1), "r"(a2), "r"(a3), "r"(b0), "r"(b1));
}

// ---------------------------------------------------------------------------
// Fused prepass: RN-convert x|Wq|Wk|Wv|Wo -> g_xT, g_Wt in ONE launch.
// ---------------------------------------------------------------------------
namespace {
constexpr int NX4 = NTOK * DM / 4;   // 2097152 float4 (x)
constexpr int NW4 = WQKV / 4;        // 65536 float4 per weight
constexpr int NTOT4 = NX4 + 4 * NW4; // 2359296
}

__global__ __launch_bounds__(256) void cvt_all(
    const float4* __restrict__ x,  const float4* __restrict__ wq,
    const float4* __restrict__ wk, const float4* __restrict__ wv,
    const float4* __restrict__ wo)
{
    const int i = blockIdx.x * 256 + threadIdx.x;
    if (i >= NTOT4) return;
    const float4* src;
    float4* dst;
    if (i < NX4) {
        src = x + i;
        dst = (float4*)g_xT + i;
    } else {
        const int j = i - NX4;
        const int region = j >> 16;      // / NW4
        const int off = j & (NW4 - 1);
        src = (region == 0 ? wq : region == 1 ? wk : region == 2 ? wv : wo) + off;
        dst = (float4*)g_Wt + j;
    }
    float4 v = *src;
    *dst = make_float4(rnd_tf32(v.x), rnd_tf32(v.y), rnd_tf32(v.z), rnd_tf32(v.w));
}

// ---------------------------------------------------------------------------
// tf32 mma.sync GEMM, BK=32, 3-stage cp.async pipeline, ONE barrier per iter.
// CTA tile 128x128, 4 warps (2m x 2n), warp tile 64x64, 128 threads (R8 cfg).
// Safety of issue-after-sync: buffer (kt+2)%3 was last read in iter kt-1;
// any warp past iter kt's sync has finished iter kt-1's compute.
// MODE 0: qkv — A = g_xT; logical B [1536,512] from g_Wt; scatter tf32-rounded
//         results to g_Q/g_K/g_V.
// MODE 1: oproj — A = g_att (tf32-rounded); B = Wo in g_Wt; output = d_out.
// ---------------------------------------------------------------------------
template <int MODE>
__global__ __launch_bounds__(128, 2) void gemm_mma(float* __restrict__ outp)
{
    extern __shared__ float gsm[];
    float* Asm = gsm;                  // 3 stages of [BM][ASTR]
    float* Bsm = gsm + 3 * ABUFS;      // 3 stages of [BK][BSTR]

    const int tid  = threadIdx.x;
    const int wid  = tid >> 5;
    const int lane = tid & 31;
    const int g    = lane >> 2;
    const int tg   = lane & 3;
    const int warp_m = wid & 1;
    const int warp_n = wid >> 1;

    const int mtile = blockIdx.x * BM;
    const int ntile = blockIdx.y * BN;

    const float* A = (MODE == 0) ? g_xT : g_att;
    int which = 0, nbase = 0;
    if (MODE == 0) { which = ntile >> 9; nbase = ntile & 511; }

    // per-thread cp.async chunks: 8 for A, 8 for B (BK=32 tile, 128 threads)
    const float* asrc[8];
    uint32_t adst[8];
    const float* bsrc[8];
    uint32_t bdst[8];
    const int bk_adv = (MODE == 0) ? DK : DM;

    #pragma unroll
    for (int j = 0; j < 8; ++j) {
        const int ia = j * 128 + tid;            // 0..1023
        const int ar = ia >> 3, ac = (ia & 7) * 4;
        asrc[j] = A + (size_t)(mtile + ar) * DM + ac;
        adst[j] = smem_u32(&Asm[ar * ASTR + ac]);

        const int bk = ia >> 5, bn = (ia & 31) * 4;
        if (MODE == 0) {
            const int nloc = nbase + bn;
            const int h = nloc >> 6, dd = nloc & 63;
            bsrc[j] = g_Wt + (size_t)which * WQKV + (size_t)h * DM * DK + (size_t)bk * DK + dd;
        } else {
            bsrc[j] = g_Wt + WO_OFF + (size_t)bk * DM + ntile + bn;
        }
        bdst[j] = smem_u32(&Bsm[bk * BSTR + bn]);
    }

    auto issue = [&](int kt) {
        const int buf = kt % 3;
        const uint32_t ao = (uint32_t)buf * ABUFS * 4;
        const uint32_t bo = (uint32_t)buf * BBUFS * 4;
        const int k0 = kt * BK;
        #pragma unroll
        for (int j = 0; j < 8; ++j) cp16(adst[j] + ao, asrc[j] + k0);
        #pragma unroll
        for (int j = 0; j < 8; ++j) cp16(bdst[j] + bo, bsrc[j] + (size_t)k0 * bk_adv);
        cp_commit();
    };

    float acc[4][8][4];
    #pragma unroll
    for (int i = 0; i < 4; ++i)
        #pragma unroll
        for (int j = 0; j < 8; ++j)
            #pragma unroll
            for (int q = 0; q < 4; ++q) acc[i][j][q] = 0.0f;

    issue(0);
    issue(1);

    for (int kt = 0; kt < KITERS; ++kt) {
        cp_wait1();          // group kt complete (only kt+1 may be pending)
        __syncthreads();     // single barrier per iteration
        if (kt + 2 < KITERS) issue(kt + 2);   // safe: see header comment
        else                 cp_commit();     // keep group count aligned

        const int buf = kt % 3;
        const float* Ab = Asm + buf * ABUFS;
        const float* Bb = Bsm + buf * BBUFS;

        #pragma unroll
        for (int ks = 0; ks < 4; ++ks) {
            const int k8 = ks * 8;
            uint32_t af[4][4];
            #pragma unroll
            for (int im = 0; im < 4; ++im) {
                const int rb = warp_m * 64 + im * 16;
                af[im][0] = __float_as_uint(Ab[(rb + g    ) * ASTR + k8 + tg    ]);
                af[im][1] = __float_as_uint(Ab[(rb + g + 8) * ASTR + k8 + tg    ]);
                af[im][2] = __float_as_uint(Ab[(rb + g    ) * ASTR + k8 + tg + 4]);
                af[im][3] = __float_as_uint(Ab[(rb + g + 8) * ASTR + k8 + tg + 4]);
            }
            #pragma unroll
            for (int in = 0; in < 8; ++in) {
                const int cb = warp_n * 64 + in * 8;
                const uint32_t b0 = __float_as_uint(Bb[(k8 + tg    ) * BSTR + cb + g]);
                const uint32_t b1 = __float_as_uint(Bb[(k8 + tg + 4) * BSTR + cb + g]);
                #pragma unroll
                for (int im = 0; im < 4; ++im)
                    mma_tf32(acc[im][in][0], acc[im][in][1], acc[im][in][2], acc[im][in][3],
                             af[im][0], af[im][1], af[im][2], af[im][3], b0, b1);
            }
        }
    }

    // ---- epilogue ----
    #pragma unroll
    for (int im = 0; im < 4; ++im) {
        const int r0 = mtile + warp_m * 64 + im * 16 + g;
        #pragma unroll
        for (int in = 0; in < 8; ++in) {
            const int c = warp_n * 64 + in * 8 + 2 * tg;
            if (MODE == 0) {
                // write tf32-rounded so attention can consume raw bits
                const int nloc = nbase + c;
                const int h = nloc >> 6, d0 = nloc & 63;
                float* gout = (which == 0) ? g_Q : (which == 1) ? g_K : g_V;
                {
                    const int b = r0 >> 8, t = r0 & 255;
                    float2 v = make_float2(rnd_tf32(acc[im][in][0]), rnd_tf32(acc[im][in][1]));
                    *(float2*)(gout + ((size_t)(b * H_ + h) * T_ + t) * DK + d0) = v;
                }
                {
                    const int r1 = r0 + 8;
                    const int b = r1 >> 8, t = r1 & 255;
                    float2 v = make_float2(rnd_tf32(acc[im][in][2]), rnd_tf32(acc[im][in][3]));
                    *(float2*)(gout + ((size_t)(b * H_ + h) * T_ + t) * DK + d0) = v;
                }
            } else {
                float2 v0 = make_float2(acc[im][in][0], acc[im][in][1]);
                float2 v1 = make_float2(acc[im][in][2], acc[im][in][3]);
                *(float2*)(outp + (size_t)r0 * DM + ntile + c) = v0;
                *(float2*)(outp + (size_t)(r0 + 8) * DM + ntile + c) = v1;
            }
        }
    }
}

// ---------------------------------------------------------------------------
// Flash attention, mma.sync tf32, STREAMED K/V (cp.async, 64-row double buffer).
// grid = B*H*2.  CTA = (bh, 128-query half).  8 warps x 16 rows.
// Q/K/V are already tf32-rounded by the qkv epilogue -> zero conversions here.
// ---------------------------------------------------------------------------
namespace {
constexpr int KVP  = 68;
constexpr int PP   = 68;
constexpr int KBUF = 64 * KVP;                       // floats per K (or V) stage
constexpr int AV_OFF = 2 * KBUF;                     // V region (floats)
constexpr int AP_OFF = 4 * KBUF;                     // P region (floats)
constexpr int ATT_SMEM_BYTES = (4 * KBUF + 8 * 16 * PP) * 4;  // 104448
}

__global__ __launch_bounds__(256, 2) void attn_kernel()
{
    extern __shared__ uint32_t smu[];

    const int bid   = blockIdx.x;
    const int bh    = bid >> 1;
    const int qbase = (bid & 1) * 128;
    const int b = bh >> 3;
    const int h = bh & 7;
    const size_t base = (size_t)bh * T_ * DK;

    const int tid  = threadIdx.x;
    const int wid  = tid >> 5;
    const int lane = tid & 31;
    const int g    = lane >> 2;
    const int tg   = lane & 3;

    uint32_t* Pw = smu + AP_OFF + wid * 16 * PP;

    // per-thread cp.async chunk map: 4 chunks for K + 4 for V per 64-row block
    int cr[4], cc[4];
    uint32_t kdst[4], vdst[4];
    #pragma unroll
    for (int j = 0; j < 4; ++j) {
        const int idx = j * 256 + tid;     // 1024 chunks = 64 rows x 16 quads
        cr[j] = idx >> 4;
        cc[j] = (idx & 15) * 4;
        kdst[j] = smem_u32(&smu[cr[j] * KVP + cc[j]]);
        vdst[j] = smem_u32(&smu[AV_OFF + cr[j] * KVP + cc[j]]);
    }

    auto issue = [&](int blk, int buf) {
        const uint32_t off = (uint32_t)buf * KBUF * 4;
        const float* ksrc = g_K + base + (size_t)(blk * 64) * DK;
        const float* vsrc = g_V + base + (size_t)(blk * 64) * DK;
        #pragma unroll
        for (int j = 0; j < 4; ++j) cp16(kdst[j] + off, ksrc + cr[j] * DK + cc[j]);
        #pragma unroll
        for (int j = 0; j < 4; ++j) cp16(vdst[j] + off, vsrc + cr[j] * DK + cc[j]);
        cp_commit();
    };

    const int nblk = (qbase + 128) >> 6;     // 2 or 4
    issue(0, 0);

    // ---- Q fragments: raw loads (bits are already tf32) ----
    const int rw = qbase + wid * 16;
    const int rA = rw + g;
    uint32_t qf[8][4];
    {
        const float* gq = g_Q + base;
        #pragma unroll
        for (int kk = 0; kk < 8; ++kk) {
            const int c = kk * 8 + tg;
            qf[kk][0] = __float_as_uint(gq[(size_t)rA * DK + c]);
            qf[kk][1] = __float_as_uint(gq[(size_t)(rA + 8) * DK + c]);
            qf[kk][2] = __float_as_uint(gq[(size_t)rA * DK + c + 4]);
            qf[kk][3] = __float_as_uint(gq[(size_t)(rA + 8) * DK + c + 4]);
        }
    }

    const float scale = 0.04419417382415922f;   // 1/sqrt(512)

    float mA = -CUDART_INF_F, mB = -CUDART_INF_F;
    float lA = 0.0f, lB = 0.0f;
    float o[8][4];
    #pragma unroll
    for (int in = 0; in < 8; ++in)
        #pragma unroll
        for (int j = 0; j < 4; ++j) o[in][j] = 0.0f;

    for (int blk = 0; blk < nblk; ++blk) {
        cp_wait0();
        __syncthreads();
        if (blk + 1 < nblk) issue(blk + 1, (blk + 1) & 1);

        const int s0 = blk * 64;
        if (s0 <= rw + 15) {
            const uint32_t* Kb = smu + (blk & 1) * KBUF;
            const uint32_t* Vb = smu + AV_OFF + (blk & 1) * KBUF;

            // ---- S = Q K^T (16 x 64) ----
            float sc[8][4];
            #pragma unroll
            for (int in = 0; in < 8; ++in)
                #pragma unroll
                for (int j = 0; j < 4; ++j) sc[in][j] = 0.0f;

            #pragma unroll
            for (int kk = 0; kk < 8; ++kk) {
                const int c = kk * 8 + tg;
                #pragma unroll
                for (int in = 0; in < 8; ++in) {
                    const int sl = in * 8 + g;
                    const uint32_t b0 = Kb[sl * KVP + c];
                    const uint32_t b1 = Kb[sl * KVP + c + 4];
                    mma_tf32(sc[in][0], sc[in][1], sc[in][2], sc[in][3],
                             qf[kk][0], qf[kk][1], qf[kk][2], qf[kk][3], b0, b1);
                }
            }

            // ---- scale + causal mask ----
            const bool need_mask = (rw - s0) < 64;
            #pragma unroll
            for (int in = 0; in < 8; ++in) {
                const int c0 = s0 + in * 8 + 2 * tg;
                if (need_mask) {
                    sc[in][0] = (c0     <= rA    ) ? sc[in][0] * scale : -CUDART_INF_F;
                    sc[in][1] = (c0 + 1 <= rA    ) ? sc[in][1] * scale : -CUDART_INF_F;
                    sc[in][2] = (c0     <= rA + 8) ? sc[in][2] * scale : -CUDART_INF_F;
                    sc[in][3] = (c0 + 1 <= rA + 8) ? sc[in][3] * scale : -CUDART_INF_F;
                } else {
                    sc[in][0] *= scale; sc[in][1] *= scale;
                    sc[in][2] *= scale; sc[in][3] *= scale;
                }
            }

            // ---- row max ----
            float bmA = -CUDART_INF_F, bmB = -CUDART_INF_F;
            #pragma unroll
            for (int in = 0; in < 8; ++in) {
                bmA = fmaxf(bmA, fmaxf(sc[in][0], sc[in][1]));
                bmB = fmaxf(bmB, fmaxf(sc[in][2], sc[in][3]));
            }
            bmA = fmaxf(bmA, __shfl_xor_sync(0xffffffffu, bmA, 1));
            bmA = fmaxf(bmA, __shfl_xor_sync(0xffffffffu, bmA, 2));
            bmB = fmaxf(bmB, __shfl_xor_sync(0xffffffffu, bmB, 1));
            bmB = fmaxf(bmB, __shfl_xor_sync(0xffffffffu, bmB, 2));

            const float nmA = fmaxf(mA, bmA);
            const float nmB = fmaxf(mB, bmB);
            const float corrA = __expf(mA - nmA);
            const float corrB = __expf(mB - nmB);
            mA = nmA; mB = nmB;

            // ---- exp, row sums, P -> per-warp smem (tf32) ----
            float bsA = 0.0f, bsB = 0.0f;
            #pragma unroll
            for (int in = 0; in < 8; ++in) {
                const float p0 = __expf(sc[in][0] - nmA);
                const float p1 = __expf(sc[in][1] - nmA);
                const float p2 = __expf(sc[in][2] - nmB);
                const float p3 = __expf(sc[in][3] - nmB);
                bsA += p0 + p1;
                bsB += p2 + p3;
                const int col = in * 8 + 2 * tg;
                uint2 wA = make_uint2(f2tf32(p0), f2tf32(p1));
                uint2 wB = make_uint2(f2tf32(p2), f2tf32(p3));
                *(uint2*)(Pw + g * PP + col)       = wA;
                *(uint2*)(Pw + (g + 8) * PP + col) = wB;
            }
            bsA += __shfl_xor_sync(0xffffffffu, bsA, 1);
            bsA += __shfl_xor_sync(0xffffffffu, bsA, 2);
            bsB += __shfl_xor_sync(0xffffffffu, bsB, 1);
            bsB += __shfl_xor_sync(0xffffffffu, bsB, 2);
            lA = lA * corrA + bsA;
            lB = lB * corrB + bsB;

            // ---- rescale O ----
            #pragma unroll
            for (int in = 0; in < 8; ++in) {
                o[in][0] *= corrA; o[in][1] *= corrA;
                o[in][2] *= corrB; o[in][3] *= corrB;
            }

            __syncwarp();

            // ---- O += P V ----
            #pragma unroll
            for (int kk = 0; kk < 8; ++kk) {
                const int pc = kk * 8 + tg;
                const uint32_t a0 = Pw[g * PP + pc];
                const uint32_t a1 = Pw[(g + 8) * PP + pc];
                const uint32_t a2 = Pw[g * PP + pc + 4];
                const uint32_t a3 = Pw[(g + 8) * PP + pc + 4];
                #pragma unroll
                for (int in = 0; in < 8; ++in) {
                    const int sl = kk * 8 + tg;
                    const uint32_t b0 = Vb[sl * KVP + in * 8 + g];
                    const uint32_t b1 = Vb[(sl + 4) * KVP + in * 8 + g];
                    mma_tf32(o[in][0], o[in][1], o[in][2], o[in][3],
                             a0, a1, a2, a3, b0, b1);
                }
            }
            __syncwarp();
        }
    }

    // ---- normalize, tf32-round, write concat layout ----
    const float invA = 1.0f / lA;
    const float invB = 1.0f / lB;
    float* opA = g_att + (size_t)(b * T_ + rA) * DM + h * DK;
    float* opB = g_att + (size_t)(b * T_ + rA + 8) * DM + h * DK;
    #pragma unroll
    for (int in = 0; in < 8; ++in) {
        const int c = in * 8 + 2 * tg;
        *(float2*)(opA + c) = make_float2(rnd_tf32(o[in][0] * invA), rnd_tf32(o[in][1] * invA));
        *(float2*)(opB + c) = make_float2(rnd_tf32(o[in][2] * invB), rnd_tf32(o[in][3] * invB));
    }
}

// ---------------------------------------------------------------------------
extern "C" void kernel_launch(void* const* d_in, const int* in_sizes, int n_in,
                              void* d_out, int out_size)
{
    const float* x  = (const float*)d_in[0];
    const float* Wq = (const float*)d_in[1];
    const float* Wk = (const float*)d_in[2];
    const float* Wv = (const float*)d_in[3];
    const float* Wo = (const float*)d_in[4];
    float* out = (float*)d_out;

    static bool attrs_done = false;
    if (!attrs_done) {
        cudaFuncSetAttribute(attn_kernel, cudaFuncAttributeMaxDynamicSharedMemorySize,
                             ATT_SMEM_BYTES);
        cudaFuncSetAttribute(gemm_mma<0>, cudaFuncAttributeMaxDynamicSharedMemorySize,
                             GEMM_SMEM);
        cudaFuncSetAttribute(gemm_mma<1>, cudaFuncAttributeMaxDynamicSharedMemorySize,
                             GEMM_SMEM);
        attrs_done = true;
    }

    // 0. fused prepass: RN-convert all inputs to tf32-rounded fp32 (1 launch)
    cvt_all<<<(NTOT4 + 255) / 256, 256>>>((const float4*)x, (const float4*)Wq,
                                          (const float4*)Wk, (const float4*)Wv,
                                          (const float4*)Wo);

    // 1. QKV projections: logical GEMM 16384 x 1536 x 512
    gemm_mma<0><<<dim3(NTOK / BM, (3 * DM) / BN), 128, GEMM_SMEM>>>(nullptr);

    // 2. flash attention (streamed K/V)
    attn_kernel<<<B_ * H_ * 2, 256, ATT_SMEM_BYTES>>>();

    // 3. output projection: 16384 x 512 x 512
    gemm_mma<1><<<dim3(NTOK / BM, DM / BN), 128, GEMM_SMEM>>>(out);
}

// round 11
// speedup vs baseline: 1.5110x; 1.5110x over previous
#include <cuda_runtime.h>
#include <math_constants.h>
#include <cstdint>

// ---------------------------------------------------------------------------
// Problem constants
// ---------------------------------------------------------------------------
namespace {
constexpr int B_  = 64;
constexpr int T_  = 256;
constexpr int DM  = 512;   // d_model
constexpr int H_  = 8;     // heads
constexpr int DK  = 64;    // head dim
constexpr int NTOK = B_ * T_;  // 16384

constexpr int BM = 128, BN = 128, BK = 32;
constexpr int KITERS = DM / BK;   // 16
constexpr int ASTR = 36;          // A smem row stride (floats)  [m][k]
constexpr int BSTR = 136;         // B smem k-row stride (floats) [k][n]
constexpr int ABUFS = BM * ASTR;  // 4608 floats per stage
constexpr int BBUFS = BK * BSTR;  // 4352 floats per stage
constexpr int GEMM_SMEM = 2 * (ABUFS + BBUFS) * 4;   // 71680 B (R8 config)
constexpr int WQKV = H_ * DM * DK;   // 262144
constexpr int WO_OFF = 3 * WQKV;
}

// Scratch (device globals — no allocation allowed in kernel_launch)
__device__ float g_Q[B_ * H_ * T_ * DK];
__device__ float g_K[B_ * H_ * T_ * DK];
__device__ float g_V[B_ * H_ * T_ * DK];
__device__ float g_att[NTOK * DM];
__device__ float g_xT[NTOK * DM];              // tf32-rounded x
__device__ float g_Wt[3 * WQKV + DM * DM];     // tf32-rounded Wq|Wk|Wv|Wo

// ---------------------------------------------------------------------------
// Helpers
// ---------------------------------------------------------------------------
__device__ __forceinline__ uint32_t f2tf32(float f) {
    uint32_t r;
    asm("cvt.rna.tf32.f32 %0, %1;" : "=r"(r) : "f"(f));
    return r;
}
__device__ __forceinline__ float rnd_tf32(float f) {
    return __uint_as_float(f2tf32(f));
}

__device__ __forceinline__ uint32_t smem_u32(const void* p) {
    uint32_t a;
    asm("{ .reg .u64 t; cvta.to.shared.u64 t, %1; cvt.u32.u64 %0, t; }"
        : "=r"(a) : "l"(p));
    return a;
}

__device__ __forceinline__ void cp16(uint32_t dst, const float* src) {
    asm volatile("cp.async.cg.shared.global [%0], [%1], 16;"
                 :: "r"(dst), "l"(src) : "memory");
}
__device__ __forceinline__ void cp_commit() {
    asm volatile("cp.async.commit_group;" ::: "memory");
}
__device__ __forceinline__ void cp_wait0() {
    asm volatile("cp.async.wait_group 0;" ::: "memory");
}
__device__ __forceinline__ void cp_wait1() {
    asm volatile("cp.async.wait_group 1;" ::: "memory");
}

__device__ __forceinline__ void mma_tf32(float& d0, float& d1, float& d2, float& d3,
                                         uint32_t a0, uint32_t a1, uint32_t a2, uint32_t a3,
                                         uint32_t b0, uint32_t b1) {
    asm volatile(
        "mma.sync.aligned.m16n8k8.row.col.f32.tf32.tf32.f32 "
        "{%0,%1,%2,%3}, {%4,%5,%6,%7}, {%8,%9}, {%0,%1,%2,%3};"
        : "+f"(d0), "+f"(d1), "+f"(d2), "+f"(d3)
        : "r"(a0), "r"(a1), "r"(a2), "r"(a3), "r"(b0), "r"(b1));
}

// ---------------------------------------------------------------------------
// Fused prepass: RN-convert x|Wq|Wk|Wv|Wo -> g_xT, g_Wt in ONE launch.
// ---------------------------------------------------------------------------
namespace {
constexpr int NX4 = NTOK * DM / 4;   // 2097152 float4 (x)
constexpr int NW4 = WQKV / 4;        // 65536 float4 per weight
constexpr int NTOT4 = NX4 + 4 * NW4; // 2359296
}

__global__ __launch_bounds__(256) void cvt_all(
    const float4* __restrict__ x,  const float4* __restrict__ wq,
    const float4* __restrict__ wk, const float4* __restrict__ wv,
    const float4* __restrict__ wo)
{
    const int i = blockIdx.x * 256 + threadIdx.x;
    if (i >= NTOT4) return;
    const float4* src;
    float4* dst;
    if (i < NX4) {
        src = x + i;
        dst = (float4*)g_xT + i;
    } else {
        const int j = i - NX4;
        const int region = j >> 16;      // / NW4
        const int off = j & (NW4 - 1);
        src = (region == 0 ? wq : region == 1 ? wk : region == 2 ? wv : wo) + off;
        dst = (float4*)g_Wt + j;
    }
    float4 v = *src;
    *dst = make_float4(rnd_tf32(v.x), rnd_tf32(v.y), rnd_tf32(v.z), rnd_tf32(v.w));
}

// ---------------------------------------------------------------------------
// tf32 mma.sync GEMM — EXACT R8 config (best measured): BK=32, 2-stage
// cp.async pipeline (kt&1 static addressing), CTA 128x128, 4 warps (2m x 2n),
// warp tile 64x64, 128 threads, 2 CTAs/SM.
// MODE 0: qkv — A = g_xT; logical B [1536,512] from g_Wt; scatter tf32-rounded
//         results to g_Q/g_K/g_V.
// MODE 1: oproj — A = g_att (tf32-rounded); B = Wo in g_Wt; output = d_out.
// ---------------------------------------------------------------------------
template <int MODE>
__global__ __launch_bounds__(128, 2) void gemm_mma(float* __restrict__ outp)
{
    extern __shared__ float gsm[];
    float* Asm = gsm;                  // 2 stages of [BM][ASTR]
    float* Bsm = gsm + 2 * ABUFS;      // 2 stages of [BK][BSTR]

    const int tid  = threadIdx.x;
    const int wid  = tid >> 5;
    const int lane = tid & 31;
    const int g    = lane >> 2;
    const int tg   = lane & 3;
    const int warp_m = wid & 1;
    const int warp_n = wid >> 1;

    const int mtile = blockIdx.x * BM;
    const int ntile = blockIdx.y * BN;

    const float* A = (MODE == 0) ? g_xT : g_att;
    int which = 0, nbase = 0;
    if (MODE == 0) { which = ntile >> 9; nbase = ntile & 511; }

    // per-thread cp.async chunks: 8 for A, 8 for B (BK=32 tile, 128 threads)
    const float* asrc[8];
    uint32_t adst[8];
    const float* bsrc[8];
    uint32_t bdst[8];
    const int bk_adv = (MODE == 0) ? DK : DM;

    #pragma unroll
    for (int j = 0; j < 8; ++j) {
        const int ia = j * 128 + tid;            // 0..1023
        const int ar = ia >> 3, ac = (ia & 7) * 4;
        asrc[j] = A + (size_t)(mtile + ar) * DM + ac;
        adst[j] = smem_u32(&Asm[ar * ASTR + ac]);

        const int bk = ia >> 5, bn = (ia & 31) * 4;
        if (MODE == 0) {
            const int nloc = nbase + bn;
            const int h = nloc >> 6, dd = nloc & 63;
            bsrc[j] = g_Wt + (size_t)which * WQKV + (size_t)h * DM * DK + (size_t)bk * DK + dd;
        } else {
            bsrc[j] = g_Wt + WO_OFF + (size_t)bk * DM + ntile + bn;
        }
        bdst[j] = smem_u32(&Bsm[bk * BSTR + bn]);
    }

    auto issue = [&](int kt) {
        const int buf = kt & 1;
        const uint32_t ao = (uint32_t)buf * ABUFS * 4;
        const uint32_t bo = (uint32_t)buf * BBUFS * 4;
        const int k0 = kt * BK;
        #pragma unroll
        for (int j = 0; j < 8; ++j) cp16(adst[j] + ao, asrc[j] + k0);
        #pragma unroll
        for (int j = 0; j < 8; ++j) cp16(bdst[j] + bo, bsrc[j] + (size_t)k0 * bk_adv);
        cp_commit();
    };

    float acc[4][8][4];
    #pragma unroll
    for (int i = 0; i < 4; ++i)
        #pragma unroll
        for (int j = 0; j < 8; ++j)
            #pragma unroll
            for (int q = 0; q < 4; ++q) acc[i][j][q] = 0.0f;

    issue(0);
    issue(1);

    for (int kt = 0; kt < KITERS; ++kt) {
        cp_wait1();          // group kt done; kt+1 may be pending
        __syncthreads();

        const int buf = kt & 1;
        const float* Ab = Asm + buf * ABUFS;
        const float* Bb = Bsm + buf * BBUFS;

        #pragma unroll
        for (int ks = 0; ks < 4; ++ks) {
            const int k8 = ks * 8;
            uint32_t af[4][4];
            #pragma unroll
            for (int im = 0; im < 4; ++im) {
                const int rb = warp_m * 64 + im * 16;
                af[im][0] = __float_as_uint(Ab[(rb + g    ) * ASTR + k8 + tg    ]);
                af[im][1] = __float_as_uint(Ab[(rb + g + 8) * ASTR + k8 + tg    ]);
                af[im][2] = __float_as_uint(Ab[(rb + g    ) * ASTR + k8 + tg + 4]);
                af[im][3] = __float_as_uint(Ab[(rb + g + 8) * ASTR + k8 + tg + 4]);
            }
            #pragma unroll
            for (int in = 0; in < 8; ++in) {
                const int cb = warp_n * 64 + in * 8;
                const uint32_t b0 = __float_as_uint(Bb[(k8 + tg    ) * BSTR + cb + g]);
                const uint32_t b1 = __float_as_uint(Bb[(k8 + tg + 4) * BSTR + cb + g]);
                #pragma unroll
                for (int im = 0; im < 4; ++im)
                    mma_tf32(acc[im][in][0], acc[im][in][1], acc[im][in][2], acc[im][in][3],
                             af[im][0], af[im][1], af[im][2], af[im][3], b0, b1);
            }
        }

        __syncthreads();     // all warps done with stage buf before overwrite
        if (kt + 2 < KITERS) issue(kt + 2);
        else                 cp_commit();   // empty group keeps count aligned
    }

    // ---- epilogue ----
    #pragma unroll
    for (int im = 0; im < 4; ++im) {
        const int r0 = mtile + warp_m * 64 + im * 16 + g;
        #pragma unroll
        for (int in = 0; in < 8; ++in) {
            const int c = warp_n * 64 + in * 8 + 2 * tg;
            if (MODE == 0) {
                // write tf32-rounded so attention can consume raw bits
                const int nloc = nbase + c;
                const int h = nloc >> 6, d0 = nloc & 63;
                float* gout = (which == 0) ? g_Q : (which == 1) ? g_K : g_V;
                {
                    const int b = r0 >> 8, t = r0 & 255;
                    float2 v = make_float2(rnd_tf32(acc[im][in][0]), rnd_tf32(acc[im][in][1]));
                    *(float2*)(gout + ((size_t)(b * H_ + h) * T_ + t) * DK + d0) = v;
                }
                {
                    const int r1 = r0 + 8;
                    const int b = r1 >> 8, t = r1 & 255;
                    float2 v = make_float2(rnd_tf32(acc[im][in][2]), rnd_tf32(acc[im][in][3]));
                    *(float2*)(gout + ((size_t)(b * H_ + h) * T_ + t) * DK + d0) = v;
                }
            } else {
                float2 v0 = make_float2(acc[im][in][0], acc[im][in][1]);
                float2 v1 = make_float2(acc[im][in][2], acc[im][in][3]);
                *(float2*)(outp + (size_t)r0 * DM + ntile + c) = v0;
                *(float2*)(outp + (size_t)(r0 + 8) * DM + ntile + c) = v1;
            }
        }
    }
}

// ---------------------------------------------------------------------------
// Flash attention, mma.sync tf32, STREAMED K/V (cp.async, 64-row double buffer).
// FUSED q-halves: grid = B*H (512 CTAs), 512 threads = 16 warps x 16 q-rows.
// K/V for each (b,h) is streamed ONCE (was 1.5x with split halves).
// Per-warp math identical to previous round -> bit-identical results.
// smem = 136 KB -> 1 CTA/SM (16 warps/SM, same as before).
// ---------------------------------------------------------------------------
namespace {
constexpr int KVP  = 68;
constexpr int PP   = 68;
constexpr int KBUF = 64 * KVP;                       // floats per K (or V) stage
constexpr int AV_OFF = 2 * KBUF;                     // V region (floats)
constexpr int AP_OFF = 4 * KBUF;                     // P region (floats)
constexpr int ATT_SMEM_BYTES = (4 * KBUF + 16 * 16 * PP) * 4;  // 139264
}

__global__ __launch_bounds__(512, 1) void attn_kernel()
{
    extern __shared__ uint32_t smu[];

    const int bh = blockIdx.x;                // 0..511
    const int b = bh >> 3;
    const int h = bh & 7;
    const size_t base = (size_t)bh * T_ * DK;

    const int tid  = threadIdx.x;
    const int wid  = tid >> 5;                // 0..15
    const int lane = tid & 31;
    const int g    = lane >> 2;
    const int tg   = lane & 3;

    uint32_t* Pw = smu + AP_OFF + wid * 16 * PP;

    // per-thread cp.async chunk map: 2 chunks for K + 2 for V per 64-row block
    int cr[2], cc[2];
    uint32_t kdst[2], vdst[2];
    #pragma unroll
    for (int j = 0; j < 2; ++j) {
        const int idx = j * 512 + tid;     // 1024 chunks = 64 rows x 16 quads
        cr[j] = idx >> 4;
        cc[j] = (idx & 15) * 4;
        kdst[j] = smem_u32(&smu[cr[j] * KVP + cc[j]]);
        vdst[j] = smem_u32(&smu[AV_OFF + cr[j] * KVP + cc[j]]);
    }

    auto issue = [&](int blk, int buf) {
        const uint32_t off = (uint32_t)buf * KBUF * 4;
        const float* ksrc = g_K + base + (size_t)(blk * 64) * DK;
        const float* vsrc = g_V + base + (size_t)(blk * 64) * DK;
        #pragma unroll
        for (int j = 0; j < 2; ++j) cp16(kdst[j] + off, ksrc + cr[j] * DK + cc[j]);
        #pragma unroll
        for (int j = 0; j < 2; ++j) cp16(vdst[j] + off, vsrc + cr[j] * DK + cc[j]);
        cp_commit();
    };

    constexpr int nblk = T_ / 64;            // 4
    issue(0, 0);

    // ---- Q fragments: raw loads (bits are already tf32) ----
    const int rw = wid * 16;                 // warp's base query row (0..240)
    const int rA = rw + g;
    uint32_t qf[8][4];
    {
        const float* gq = g_Q + base;
        #pragma unroll
        for (int kk = 0; kk < 8; ++kk) {
            const int c = kk * 8 + tg;
            qf[kk][0] = __float_as_uint(gq[(size_t)rA * DK + c]);
            qf[kk][1] = __float_as_uint(gq[(size_t)(rA + 8) * DK + c]);
            qf[kk][2] = __float_as_uint(gq[(size_t)rA * DK + c + 4]);
            qf[kk][3] = __float_as_uint(gq[(size_t)(rA + 8) * DK + c + 4]);
        }
    }

    const float scale = 0.04419417382415922f;   // 1/sqrt(512)

    float mA = -CUDART_INF_F, mB = -CUDART_INF_F;
    float lA = 0.0f, lB = 0.0f;
    float o[8][4];
    #pragma unroll
    for (int in = 0; in < 8; ++in)
        #pragma unroll
        for (int j = 0; j < 4; ++j) o[in][j] = 0.0f;

    for (int blk = 0; blk < nblk; ++blk) {
        cp_wait0();
        __syncthreads();
        if (blk + 1 < nblk) issue(blk + 1, (blk + 1) & 1);

        const int s0 = blk * 64;
        if (s0 <= rw + 15) {
            const uint32_t* Kb = smu + (blk & 1) * KBUF;
            const uint32_t* Vb = smu + AV_OFF + (blk & 1) * KBUF;

            // ---- S = Q K^T (16 x 64) ----
            float sc[8][4];
            #pragma unroll
            for (int in = 0; in < 8; ++in)
                #pragma unroll
                for (int j = 0; j < 4; ++j) sc[in][j] = 0.0f;

            #pragma unroll
            for (int kk = 0; kk < 8; ++kk) {
                const int c = kk * 8 + tg;
                #pragma unroll
                for (int in = 0; in < 8; ++in) {
                    const int sl = in * 8 + g;
                    const uint32_t b0 = Kb[sl * KVP + c];
                    const uint32_t b1 = Kb[sl * KVP + c + 4];
                    mma_tf32(sc[in][0], sc[in][1], sc[in][2], sc[in][3],
                             qf[kk][0], qf[kk][1], qf[kk][2], qf[kk][3], b0, b1);
                }
            }

            // ---- scale + causal mask ----
            const bool need_mask = (rw - s0) < 64;
            #pragma unroll
            for (int in = 0; in < 8; ++in) {
                const int c0 = s0 + in * 8 + 2 * tg;
                if (need_mask) {
                    sc[in][0] = (c0     <= rA    ) ? sc[in][0] * scale : -CUDART_INF_F;
                    sc[in][1] = (c0 + 1 <= rA    ) ? sc[in][1] * scale : -CUDART_INF_F;
                    sc[in][2] = (c0     <= rA + 8) ? sc[in][2] * scale : -CUDART_INF_F;
                    sc[in][3] = (c0 + 1 <= rA + 8) ? sc[in][3] * scale : -CUDART_INF_F;
                } else {
                    sc[in][0] *= scale; sc[in][1] *= scale;
                    sc[in][2] *= scale; sc[in][3] *= scale;
                }
            }

            // ---- row max ----
            float bmA = -CUDART_INF_F, bmB = -CUDART_INF_F;
            #pragma unroll
            for (int in = 0; in < 8; ++in) {
                bmA = fmaxf(bmA, fmaxf(sc[in][0], sc[in][1]));
                bmB = fmaxf(bmB, fmaxf(sc[in][2], sc[in][3]));
            }
            bmA = fmaxf(bmA, __shfl_xor_sync(0xffffffffu, bmA, 1));
            bmA = fmaxf(bmA, __shfl_xor_sync(0xffffffffu, bmA, 2));
            bmB = fmaxf(bmB, __shfl_xor_sync(0xffffffffu, bmB, 1));
            bmB = fmaxf(bmB, __shfl_xor_sync(0xffffffffu, bmB, 2));

            const float nmA = fmaxf(mA, bmA);
            const float nmB = fmaxf(mB, bmB);
            const float corrA = __expf(mA - nmA);
            const float corrB = __expf(mB - nmB);
            mA = nmA; mB = nmB;

            // ---- exp, row sums, P -> per-warp smem (tf32) ----
            float bsA = 0.0f, bsB = 0.0f;
            #pragma unroll
            for (int in = 0; in < 8; ++in) {
                const float p0 = __expf(sc[in][0] - nmA);
                const float p1 = __expf(sc[in][1] - nmA);
                const float p2 = __expf(sc[in][2] - nmB);
                const float p3 = __expf(sc[in][3] - nmB);
                bsA += p0 + p1;
                bsB += p2 + p3;
                const int col = in * 8 + 2 * tg;
                uint2 wA = make_uint2(f2tf32(p0), f2tf32(p1));
                uint2 wB = make_uint2(f2tf32(p2), f2tf32(p3));
                *(uint2*)(Pw + g * PP + col)       = wA;
                *(uint2*)(Pw + (g + 8) * PP + col) = wB;
            }
            bsA += __shfl_xor_sync(0xffffffffu, bsA, 1);
            bsA += __shfl_xor_sync(0xffffffffu, bsA, 2);
            bsB += __shfl_xor_sync(0xffffffffu, bsB, 1);
            bsB += __shfl_xor_sync(0xffffffffu, bsB, 2);
            lA = lA * corrA + bsA;
            lB = lB * corrB + bsB;

            // ---- rescale O ----
            #pragma unroll
            for (int in = 0; in < 8; ++in) {
                o[in][0] *= corrA; o[in][1] *= corrA;
                o[in][2] *= corrB; o[in][3] *= corrB;
            }

            __syncwarp();

            // ---- O += P V ----
            #pragma unroll
            for (int kk = 0; kk < 8; ++kk) {
                const int pc = kk * 8 + tg;
                const uint32_t a0 = Pw[g * PP + pc];
                const uint32_t a1 = Pw[(g + 8) * PP + pc];
                const uint32_t a2 = Pw[g * PP + pc + 4];
                const uint32_t a3 = Pw[(g + 8) * PP + pc + 4];
                #pragma unroll
                for (int in = 0; in < 8; ++in) {
                    const int sl = kk * 8 + tg;
                    const uint32_t b0 = Vb[sl * KVP + in * 8 + g];
                    const uint32_t b1 = Vb[(sl + 4) * KVP + in * 8 + g];
                    mma_tf32(o[in][0], o[in][1], o[in][2], o[in][3],
                             a0, a1, a2, a3, b0, b1);
                }
            }
            __syncwarp();
        }
    }

    // ---- normalize, tf32-round, write concat layout ----
    const float invA = 1.0f / lA;
    const float invB = 1.0f / lB;
    float* opA = g_att + (size_t)(b * T_ + rA) * DM + h * DK;
    float* opB = g_att + (size_t)(b * T_ + rA + 8) * DM + h * DK;
    #pragma unroll
    for (int in = 0; in < 8; ++in) {
        const int c = in * 8 + 2 * tg;
        *(float2*)(opA + c) = make_float2(rnd_tf32(o[in][0] * invA), rnd_tf32(o[in][1] * invA));
        *(float2*)(opB + c) = make_float2(rnd_tf32(o[in][2] * invB), rnd_tf32(o[in][3] * invB));
    }
}

// ---------------------------------------------------------------------------
extern "C" void kernel_launch(void* const* d_in, const int* in_sizes, int n_in,
                              void* d_out, int out_size)
{
    const float* x  = (const float*)d_in[0];
    const float* Wq = (const float*)d_in[1];
    const float* Wk = (const float*)d_in[2];
    const float* Wv = (const float*)d_in[3];
    const float* Wo = (const float*)d_in[4];
    float* out = (float*)d_out;

    static bool attrs_done = false;
    if (!attrs_done) {
        cudaFuncSetAttribute(attn_kernel, cudaFuncAttributeMaxDynamicSharedMemorySize,
                             ATT_SMEM_BYTES);
        cudaFuncSetAttribute(gemm_mma<0>, cudaFuncAttributeMaxDynamicSharedMemorySize,
                             GEMM_SMEM);
        cudaFuncSetAttribute(gemm_mma<1>, cudaFuncAttributeMaxDynamicSharedMemorySize,
                             GEMM_SMEM);
        attrs_done = true;
    }

    // 0. fused prepass: RN-convert all inputs to tf32-rounded fp32 (1 launch)
    cvt_all<<<(NTOT4 + 255) / 256, 256>>>((const float4*)x, (const float4*)Wq,
                                          (const float4*)Wk, (const float4*)Wv,
                                          (const float4*)Wo);

    // 1. QKV projections: logical GEMM 16384 x 1536 x 512
    gemm_mma<0><<<dim3(NTOK / BM, (3 * DM) / BN), 128, GEMM_SMEM>>>(nullptr);

    // 2. flash attention (fused halves, streamed K/V)
    attn_kernel<<<B_ * H_, 512, ATT_SMEM_BYTES>>>();

    // 3. output projection: 16384 x 512 x 512
    gemm_mma<1><<<dim3(NTOK / BM, DM / BN), 128, GEMM_SMEM>>>(out);
}

// round 12
// speedup vs baseline: 1.6371x; 1.0835x over previous
#include <cuda_runtime.h>
#include <math_constants.h>
#include <cstdint>

// ---------------------------------------------------------------------------
// Problem constants
// ---------------------------------------------------------------------------
namespace {
constexpr int B_  = 64;
constexpr int T_  = 256;
constexpr int DM  = 512;   // d_model
constexpr int H_  = 8;     // heads
constexpr int DK  = 64;    // head dim
constexpr int NTOK = B_ * T_;  // 16384

constexpr int BM = 128, BN = 128, BK = 32;
constexpr int KITERS = DM / BK;   // 16
constexpr int ASTR = 36;          // A smem row stride (floats)  [m][k]
constexpr int BSTR = 136;         // B smem k-row stride (floats) [k][n]
constexpr int ABUFS = BM * ASTR;  // 4608 floats per stage
constexpr int BBUFS = BK * BSTR;  // 4352 floats per stage
constexpr int GEMM_SMEM = 3 * (ABUFS + BBUFS) * 4;   // 107520 B (3 stages)
constexpr int WQKV = H_ * DM * DK;   // 262144
constexpr int WO_OFF = 3 * WQKV;
}

// Scratch (device globals — no allocation allowed in kernel_launch)
__device__ float g_Q[B_ * H_ * T_ * DK];
__device__ float g_K[B_ * H_ * T_ * DK];
__device__ float g_V[B_ * H_ * T_ * DK];
__device__ float g_att[NTOK * DM];
__device__ float g_xT[NTOK * DM];              // tf32-rounded x
__device__ float g_Wt[3 * WQKV + DM * DM];     // tf32-rounded Wq|Wk|Wv|Wo

// ---------------------------------------------------------------------------
// Helpers
// ---------------------------------------------------------------------------
__device__ __forceinline__ uint32_t f2tf32(float f) {
    uint32_t r;
    asm("cvt.rna.tf32.f32 %0, %1;" : "=r"(r) : "f"(f));
    return r;
}
__device__ __forceinline__ float rnd_tf32(float f) {
    return __uint_as_float(f2tf32(f));
}

__device__ __forceinline__ uint32_t smem_u32(const void* p) {
    uint32_t a;
    asm("{ .reg .u64 t; cvta.to.shared.u64 t, %1; cvt.u32.u64 %0, t; }"
        : "=r"(a) : "l"(p));
    return a;
}

__device__ __forceinline__ void cp16(uint32_t dst, const float* src) {
    asm volatile("cp.async.cg.shared.global [%0], [%1], 16;"
                 :: "r"(dst), "l"(src) : "memory");
}
__device__ __forceinline__ void cp_commit() {
    asm volatile("cp.async.commit_group;" ::: "memory");
}
__device__ __forceinline__ void cp_wait0() {
    asm volatile("cp.async.wait_group 0;" ::: "memory");
}
__device__ __forceinline__ void cp_wait1() {
    asm volatile("cp.async.wait_group 1;" ::: "memory");
}

__device__ __forceinline__ void mma_tf32(float& d0, float& d1, float& d2, float& d3,
                                         uint32_t a0, uint32_t a1, uint32_t a2, uint32_t a3,
                                         uint32_t b0, uint32_t b1) {
    asm volatile(
        "mma.sync.aligned.m16n8k8.row.col.f32.tf32.tf32.f32 "
        "{%0,%1,%2,%3}, {%4,%5,%6,%7}, {%8,%9}, {%0,%1,%2,%3};"
        : "+f"(d0), "+f"(d1), "+f"(d2), "+f"(d3)
        : "r"(a0), "r"(a1), "r"(a2), "r"(a3), "r"(b0), "r"(b1));
}

// ---------------------------------------------------------------------------
// Fused prepass: RN-convert x|Wq|Wk|Wv|Wo -> g_xT, g_Wt in ONE launch.
// ---------------------------------------------------------------------------
namespace {
constexpr int NX4 = NTOK * DM / 4;   // 2097152 float4 (x)
constexpr int NW4 = WQKV / 4;        // 65536 float4 per weight
constexpr int NTOT4 = NX4 + 4 * NW4; // 2359296
}

__global__ __launch_bounds__(256) void cvt_all(
    const float4* __restrict__ x,  const float4* __restrict__ wq,
    const float4* __restrict__ wk, const float4* __restrict__ wv,
    const float4* __restrict__ wo)
{
    const int i = blockIdx.x * 256 + threadIdx.x;
    if (i >= NTOT4) return;
    const float4* src;
    float4* dst;
    if (i < NX4) {
        src = x + i;
        dst = (float4*)g_xT + i;
    } else {
        const int j = i - NX4;
        const int region = j >> 16;      // / NW4
        const int off = j & (NW4 - 1);
        src = (region == 0 ? wq : region == 1 ? wk : region == 2 ? wv : wo) + off;
        dst = (float4*)g_Wt + j;
    }
    float4 v = *src;
    *dst = make_float4(rnd_tf32(v.x), rnd_tf32(v.y), rnd_tf32(v.z), rnd_tf32(v.w));
}

// ---------------------------------------------------------------------------
// tf32 mma.sync GEMM — R8 tile config (128x128 CTA, 4 warps 2m x 2n, warp
// tile 64x64, BK=32, 128 threads, 2 CTAs/SM) with a 3-stage cp.async
// pipeline, ONE barrier per k-iter, and a FULLY UNROLLED k-loop so all
// stage offsets (kt%3) and global offsets (kt*BK) are compile-time constants.
// Safety of issue-after-sync: buffer (kt+2)%3 was last read in iter kt-1;
// any warp past iter kt's sync has finished iter kt-1's compute.
// MODE 0: qkv — A = g_xT; logical B [1536,512] from g_Wt; scatter tf32-rounded
//         results to g_Q/g_K/g_V.
// MODE 1: oproj — A = g_att (tf32-rounded); B = Wo in g_Wt; output = d_out.
// ---------------------------------------------------------------------------
template <int MODE>
__global__ __launch_bounds__(128, 2) void gemm_mma(float* __restrict__ outp)
{
    extern __shared__ float gsm[];
    float* Asm = gsm;                  // 3 stages of [BM][ASTR]
    float* Bsm = gsm + 3 * ABUFS;      // 3 stages of [BK][BSTR]

    const int tid  = threadIdx.x;
    const int wid  = tid >> 5;
    const int lane = tid & 31;
    const int g    = lane >> 2;
    const int tg   = lane & 3;
    const int warp_m = wid & 1;
    const int warp_n = wid >> 1;

    const int mtile = blockIdx.x * BM;
    const int ntile = blockIdx.y * BN;

    const float* A = (MODE == 0) ? g_xT : g_att;
    int which = 0, nbase = 0;
    if (MODE == 0) { which = ntile >> 9; nbase = ntile & 511; }

    // per-thread cp.async chunks: 8 for A, 8 for B (BK=32 tile, 128 threads)
    const float* asrc[8];
    uint32_t adst[8];
    const float* bsrc[8];
    uint32_t bdst[8];
    const int bk_adv = (MODE == 0) ? DK : DM;

    #pragma unroll
    for (int j = 0; j < 8; ++j) {
        const int ia = j * 128 + tid;            // 0..1023
        const int ar = ia >> 3, ac = (ia & 7) * 4;
        asrc[j] = A + (size_t)(mtile + ar) * DM + ac;
        adst[j] = smem_u32(&Asm[ar * ASTR + ac]);

        const int bk = ia >> 5, bn = (ia & 31) * 4;
        if (MODE == 0) {
            const int nloc = nbase + bn;
            const int h = nloc >> 6, dd = nloc & 63;
            bsrc[j] = g_Wt + (size_t)which * WQKV + (size_t)h * DM * DK + (size_t)bk * DK + dd;
        } else {
            bsrc[j] = g_Wt + WO_OFF + (size_t)bk * DM + ntile + bn;
        }
        bdst[j] = smem_u32(&Bsm[bk * BSTR + bn]);
    }

    auto issue = [&](int kt) {
        const int buf = kt % 3;                  // constant after unroll
        const uint32_t ao = (uint32_t)buf * (ABUFS * 4);
        const uint32_t bo = (uint32_t)buf * (BBUFS * 4);
        const int k0 = kt * BK;                  // constant after unroll
        #pragma unroll
        for (int j = 0; j < 8; ++j) cp16(adst[j] + ao, asrc[j] + k0);
        #pragma unroll
        for (int j = 0; j < 8; ++j) cp16(bdst[j] + bo, bsrc[j] + (size_t)k0 * bk_adv);
        cp_commit();
    };

    float acc[4][8][4];
    #pragma unroll
    for (int i = 0; i < 4; ++i)
        #pragma unroll
        for (int j = 0; j < 8; ++j)
            #pragma unroll
            for (int q = 0; q < 4; ++q) acc[i][j][q] = 0.0f;

    issue(0);
    issue(1);

    #pragma unroll
    for (int kt = 0; kt < KITERS; ++kt) {
        cp_wait1();          // group kt complete (only kt+1 may be pending)
        __syncthreads();     // single barrier per iteration
        if (kt + 2 < KITERS) issue(kt + 2);   // safe: see header comment
        else                 cp_commit();     // keep group count aligned

        const int buf = kt % 3;               // compile-time constant
        const float* Ab = Asm + buf * ABUFS;
        const float* Bb = Bsm + buf * BBUFS;

        #pragma unroll
        for (int ks = 0; ks < 4; ++ks) {
            const int k8 = ks * 8;
            uint32_t af[4][4];
            #pragma unroll
            for (int im = 0; im < 4; ++im) {
                const int rb = warp_m * 64 + im * 16;
                af[im][0] = __float_as_uint(Ab[(rb + g    ) * ASTR + k8 + tg    ]);
                af[im][1] = __float_as_uint(Ab[(rb + g + 8) * ASTR + k8 + tg    ]);
                af[im][2] = __float_as_uint(Ab[(rb + g    ) * ASTR + k8 + tg + 4]);
                af[im][3] = __float_as_uint(Ab[(rb + g + 8) * ASTR + k8 + tg + 4]);
            }
            #pragma unroll
            for (int in = 0; in < 8; ++in) {
                const int cb = warp_n * 64 + in * 8;
                const uint32_t b0 = __float_as_uint(Bb[(k8 + tg    ) * BSTR + cb + g]);
                const uint32_t b1 = __float_as_uint(Bb[(k8 + tg + 4) * BSTR + cb + g]);
                #pragma unroll
                for (int im = 0; im < 4; ++im)
                    mma_tf32(acc[im][in][0], acc[im][in][1], acc[im][in][2], acc[im][in][3],
                             af[im][0], af[im][1], af[im][2], af[im][3], b0, b1);
            }
        }
    }

    // ---- epilogue ----
    #pragma unroll
    for (int im = 0; im < 4; ++im) {
        const int r0 = mtile + warp_m * 64 + im * 16 + g;
        #pragma unroll
        for (int in = 0; in < 8; ++in) {
            const int c = warp_n * 64 + in * 8 + 2 * tg;
            if (MODE == 0) {
                // write tf32-rounded so attention can consume raw bits
                const int nloc = nbase + c;
                const int h = nloc >> 6, d0 = nloc & 63;
                float* gout = (which == 0) ? g_Q : (which == 1) ? g_K : g_V;
                {
                    const int b = r0 >> 8, t = r0 & 255;
                    float2 v = make_float2(rnd_tf32(acc[im][in][0]), rnd_tf32(acc[im][in][1]));
                    *(float2*)(gout + ((size_t)(b * H_ + h) * T_ + t) * DK + d0) = v;
                }
                {
                    const int r1 = r0 + 8;
                    const int b = r1 >> 8, t = r1 & 255;
                    float2 v = make_float2(rnd_tf32(acc[im][in][2]), rnd_tf32(acc[im][in][3]));
                    *(float2*)(gout + ((size_t)(b * H_ + h) * T_ + t) * DK + d0) = v;
                }
            } else {
                float2 v0 = make_float2(acc[im][in][0], acc[im][in][1]);
                float2 v1 = make_float2(acc[im][in][2], acc[im][in][3]);
                *(float2*)(outp + (size_t)r0 * DM + ntile + c) = v0;
                *(float2*)(outp + (size_t)(r0 + 8) * DM + ntile + c) = v1;
            }
        }
    }
}

// ---------------------------------------------------------------------------
// Flash attention (R8 config — best measured), mma.sync tf32, STREAMED K/V
// (cp.async, 64-row double buffer).  grid = B*H*2.  CTA = (bh, 128-q half).
// 8 warps x 16 rows.  Q/K/V already tf32-rounded -> zero conversions here.
// smem = 102 KB -> 2 CTAs/SM.
// ---------------------------------------------------------------------------
namespace {
constexpr int KVP  = 68;
constexpr int PP   = 68;
constexpr int KBUF = 64 * KVP;                       // floats per K (or V) stage
constexpr int AV_OFF = 2 * KBUF;                     // V region (floats)
constexpr int AP_OFF = 4 * KBUF;                     // P region (floats)
constexpr int ATT_SMEM_BYTES = (4 * KBUF + 8 * 16 * PP) * 4;  // 104448
}

__global__ __launch_bounds__(256, 2) void attn_kernel()
{
    extern __shared__ uint32_t smu[];

    const int bid   = blockIdx.x;
    const int bh    = bid >> 1;
    const int qbase = (bid & 1) * 128;
    const int b = bh >> 3;
    const int h = bh & 7;
    const size_t base = (size_t)bh * T_ * DK;

    const int tid  = threadIdx.x;
    const int wid  = tid >> 5;
    const int lane = tid & 31;
    const int g    = lane >> 2;
    const int tg   = lane & 3;

    uint32_t* Pw = smu + AP_OFF + wid * 16 * PP;

    // per-thread cp.async chunk map: 4 chunks for K + 4 for V per 64-row block
    int cr[4], cc[4];
    uint32_t kdst[4], vdst[4];
    #pragma unroll
    for (int j = 0; j < 4; ++j) {
        const int idx = j * 256 + tid;     // 1024 chunks = 64 rows x 16 quads
        cr[j] = idx >> 4;
        cc[j] = (idx & 15) * 4;
        kdst[j] = smem_u32(&smu[cr[j] * KVP + cc[j]]);
        vdst[j] = smem_u32(&smu[AV_OFF + cr[j] * KVP + cc[j]]);
    }

    auto issue = [&](int blk, int buf) {
        const uint32_t off = (uint32_t)buf * KBUF * 4;
        const float* ksrc = g_K + base + (size_t)(blk * 64) * DK;
        const float* vsrc = g_V + base + (size_t)(blk * 64) * DK;
        #pragma unroll
        for (int j = 0; j < 4; ++j) cp16(kdst[j] + off, ksrc + cr[j] * DK + cc[j]);
        #pragma unroll
        for (int j = 0; j < 4; ++j) cp16(vdst[j] + off, vsrc + cr[j] * DK + cc[j]);
        cp_commit();
    };

    const int nblk = (qbase + 128) >> 6;     // 2 or 4
    issue(0, 0);

    // ---- Q fragments: raw loads (bits are already tf32) ----
    const int rw = qbase + wid * 16;
    const int rA = rw + g;
    uint32_t qf[8][4];
    {
        const float* gq = g_Q + base;
        #pragma unroll
        for (int kk = 0; kk < 8; ++kk) {
            const int c = kk * 8 + tg;
            qf[kk][0] = __float_as_uint(gq[(size_t)rA * DK + c]);
            qf[kk][1] = __float_as_uint(gq[(size_t)(rA + 8) * DK + c]);
            qf[kk][2] = __float_as_uint(gq[(size_t)rA * DK + c + 4]);
            qf[kk][3] = __float_as_uint(gq[(size_t)(rA + 8) * DK + c + 4]);
        }
    }

    const float scale = 0.04419417382415922f;   // 1/sqrt(512)

    float mA = -CUDART_INF_F, mB = -CUDART_INF_F;
    float lA = 0.0f, lB = 0.0f;
    float o[8][4];
    #pragma unroll
    for (int in = 0; in < 8; ++in)
        #pragma unroll
        for (int j = 0; j < 4; ++j) o[in][j] = 0.0f;

    for (int blk = 0; blk < nblk; ++blk) {
        cp_wait0();
        __syncthreads();
        if (blk + 1 < nblk) issue(blk + 1, (blk + 1) & 1);

        const int s0 = blk * 64;
        if (s0 <= rw + 15) {
            const uint32_t* Kb = smu + (blk & 1) * KBUF;
            const uint32_t* Vb = smu + AV_OFF + (blk & 1) * KBUF;

            // ---- S = Q K^T (16 x 64) ----
            float sc[8][4];
            #pragma unroll
            for (int in = 0; in < 8; ++in)
                #pragma unroll
                for (int j = 0; j < 4; ++j) sc[in][j] = 0.0f;

            #pragma unroll
            for (int kk = 0; kk < 8; ++kk) {
                const int c = kk * 8 + tg;
                #pragma unroll
                for (int in = 0; in < 8; ++in) {
                    const int sl = in * 8 + g;
                    const uint32_t b0 = Kb[sl * KVP + c];
                    const uint32_t b1 = Kb[sl * KVP + c + 4];
                    mma_tf32(sc[in][0], sc[in][1], sc[in][2], sc[in][3],
                             qf[kk][0], qf[kk][1], qf[kk][2], qf[kk][3], b0, b1);
                }
            }

            // ---- scale + causal mask ----
            const bool need_mask = (rw - s0) < 64;
            #pragma unroll
            for (int in = 0; in < 8; ++in) {
                const int c0 = s0 + in * 8 + 2 * tg;
                if (need_mask) {
                    sc[in][0] = (c0     <= rA    ) ? sc[in][0] * scale : -CUDART_INF_F;
                    sc[in][1] = (c0 + 1 <= rA    ) ? sc[in][1] * scale : -CUDART_INF_F;
                    sc[in][2] = (c0     <= rA + 8) ? sc[in][2] * scale : -CUDART_INF_F;
                    sc[in][3] = (c0 + 1 <= rA + 8) ? sc[in][3] * scale : -CUDART_INF_F;
                } else {
                    sc[in][0] *= scale; sc[in][1] *= scale;
                    sc[in][2] *= scale; sc[in][3] *= scale;
                }
            }

            // ---- row max ----
            float bmA = -CUDART_INF_F, bmB = -CUDART_INF_F;
            #pragma unroll
            for (int in = 0; in < 8; ++in) {
                bmA = fmaxf(bmA, fmaxf(sc[in][0], sc[in][1]));
                bmB = fmaxf(bmB, fmaxf(sc[in][2], sc[in][3]));
            }
            bmA = fmaxf(bmA, __shfl_xor_sync(0xffffffffu, bmA, 1));
            bmA = fmaxf(bmA, __shfl_xor_sync(0xffffffffu, bmA, 2));
            bmB = fmaxf(bmB, __shfl_xor_sync(0xffffffffu, bmB, 1));
            bmB = fmaxf(bmB, __shfl_xor_sync(0xffffffffu, bmB, 2));

            const float nmA = fmaxf(mA, bmA);
            const float nmB = fmaxf(mB, bmB);
            const float corrA = __expf(mA - nmA);
            const float corrB = __expf(mB - nmB);
            mA = nmA; mB = nmB;

            // ---- exp, row sums, P -> per-warp smem (tf32) ----
            float bsA = 0.0f, bsB = 0.0f;
            #pragma unroll
            for (int in = 0; in < 8; ++in) {
                const float p0 = __expf(sc[in][0] - nmA);
                const float p1 = __expf(sc[in][1] - nmA);
                const float p2 = __expf(sc[in][2] - nmB);
                const float p3 = __expf(sc[in][3] - nmB);
                bsA += p0 + p1;
                bsB += p2 + p3;
                const int col = in * 8 + 2 * tg;
                uint2 wA = make_uint2(f2tf32(p0), f2tf32(p1));
                uint2 wB = make_uint2(f2tf32(p2), f2tf32(p3));
                *(uint2*)(Pw + g * PP + col)       = wA;
                *(uint2*)(Pw + (g + 8) * PP + col) = wB;
            }
            bsA += __shfl_xor_sync(0xffffffffu, bsA, 1);
            bsA += __shfl_xor_sync(0xffffffffu, bsA, 2);
            bsB += __shfl_xor_sync(0xffffffffu, bsB, 1);
            bsB += __shfl_xor_sync(0xffffffffu, bsB, 2);
            lA = lA * corrA + bsA;
            lB = lB * corrB + bsB;

            // ---- rescale O ----
            #pragma unroll
            for (int in = 0; in < 8; ++in) {
                o[in][0] *= corrA; o[in][1] *= corrA;
                o[in][2] *= corrB; o[in][3] *= corrB;
            }

            __syncwarp();

            // ---- O += P V ----
            #pragma unroll
            for (int kk = 0; kk < 8; ++kk) {
                const int pc = kk * 8 + tg;
                const uint32_t a0 = Pw[g * PP + pc];
                const uint32_t a1 = Pw[(g + 8) * PP + pc];
                const uint32_t a2 = Pw[g * PP + pc + 4];
                const uint32_t a3 = Pw[(g + 8) * PP + pc + 4];
                #pragma unroll
                for (int in = 0; in < 8; ++in) {
                    const int sl = kk * 8 + tg;
                    const uint32_t b0 = Vb[sl * KVP + in * 8 + g];
                    const uint32_t b1 = Vb[(sl + 4) * KVP + in * 8 + g];
                    mma_tf32(o[in][0], o[in][1], o[in][2], o[in][3],
                             a0, a1, a2, a3, b0, b1);
                }
            }
            __syncwarp();
        }
    }

    // ---- normalize, tf32-round, write concat layout ----
    const float invA = 1.0f / lA;
    const float invB = 1.0f / lB;
    float* opA = g_att + (size_t)(b * T_ + rA) * DM + h * DK;
    float* opB = g_att + (size_t)(b * T_ + rA + 8) * DM + h * DK;
    #pragma unroll
    for (int in = 0; in < 8; ++in) {
        const int c = in * 8 + 2 * tg;
        *(float2*)(opA + c) = make_float2(rnd_tf32(o[in][0] * invA), rnd_tf32(o[in][1] * invA));
        *(float2*)(opB + c) = make_float2(rnd_tf32(o[in][2] * invB), rnd_tf32(o[in][3] * invB));
    }
}

// ---------------------------------------------------------------------------
extern "C" void kernel_launch(void* const* d_in, const int* in_sizes, int n_in,
                              void* d_out, int out_size)
{
    const float* x  = (const float*)d_in[0];
    const float* Wq = (const float*)d_in[1];
    const float* Wk = (const float*)d_in[2];
    const float* Wv = (const float*)d_in[3];
    const float* Wo = (const float*)d_in[4];
    float* out = (float*)d_out;

    static bool attrs_done = false;
    if (!attrs_done) {
        cudaFuncSetAttribute(attn_kernel, cudaFuncAttributeMaxDynamicSharedMemorySize,
                             ATT_SMEM_BYTES);
        cudaFuncSetAttribute(gemm_mma<0>, cudaFuncAttributeMaxDynamicSharedMemorySize,
                             GEMM_SMEM);
        cudaFuncSetAttribute(gemm_mma<1>, cudaFuncAttributeMaxDynamicSharedMemorySize,
                             GEMM_SMEM);
        attrs_done = true;
    }

    // 0. fused prepass: RN-convert all inputs to tf32-rounded fp32 (1 launch)
    cvt_all<<<(NTOT4 + 255) / 256, 256>>>((const float4*)x, (const float4*)Wq,
                                          (const float4*)Wk, (const float4*)Wv,
                                          (const float4*)Wo);

    // 1. QKV projections: logical GEMM 16384 x 1536 x 512
    gemm_mma<0><<<dim3(NTOK / BM, (3 * DM) / BN), 128, GEMM_SMEM>>>(nullptr);

    // 2. flash attention (split halves, streamed K/V — R8 config)
    attn_kernel<<<B_ * H_ * 2, 256, ATT_SMEM_BYTES>>>();

    // 3. output projection: 16384 x 512 x 512
    gemm_mma<1><<<dim3(NTOK / BM, DM / BN), 128, GEMM_SMEM>>>(out);
}